// round 5
// baseline (speedup 1.0000x reference)
#include <cuda_runtime.h>
#include <cuda_bf16.h>
#include <cstdint>
#include <cstddef>

#define NN   50000
#define EE   800000
#define INC  512
#define HIDC 256
#define OUTC 40
#define BN_EPS 1e-5f
#define NP   196        // ceil(NN/256) scan partials
#define G0B  782        // GEMM0 blocks: 2 x 391
#define L40B 6250       // prop40 blocks: ceil(NN/8)

// ---------------- scratch (device globals; no allocation allowed) ----------------
__device__ float g_deg[NN];
__device__ float g_dinv[NN];
__device__ int   g_cnt[NN];
__device__ int   g_rowstart[NN + 1];
__device__ int   g_cursor[NN];
__device__ int   g_part[NP];
__device__ int   g_partscan[NP];
__device__ int   g_ecol[EE];
__device__ float g_ew2[EE];          // w * dinv[col]  (sorted by row)
__device__ float g_t1[NN * HIDC];
__device__ float g_t2[NN * HIDC];
__device__ float g_t3[NN * OUTC];
__device__ float g_la[NN * OUTC];
__device__ float g_lb[NN * OUTC];
__device__ float g_lc[NN * OUTC];
__device__ float g_ld[NN * OUTC];
__device__ float g_sum[HIDC];
__device__ float g_sumsq[HIDC];
__device__ float g_scale[HIDC];
__device__ float g_shift[HIDC];

// ---------------- CSR construction ----------------
__global__ void k_init_node() {
    int i = blockIdx.x * blockDim.x + threadIdx.x;
    if (i < NN) { g_deg[i] = 1.0f; g_cnt[i] = 0; }   // self-loop weight
}

__global__ void k_deg_cnt(const int* __restrict__ row, const float* __restrict__ w) {
    int e = blockIdx.x * blockDim.x + threadIdx.x;
    if (e < EE) {
        int r = row[e];
        atomicAdd(&g_deg[r], w[e]);
        atomicAdd(&g_cnt[r], 1);
    }
}

// -------- 3-phase parallel scan (scan1 also computes dinv) --------
__device__ __forceinline__ int block_incl_scan(int val, int* warp_sums) {
    int lane = threadIdx.x & 31, wid = threadIdx.x >> 5;
    int v = val;
#pragma unroll
    for (int o = 1; o < 32; o <<= 1) {
        int n = __shfl_up_sync(0xffffffffu, v, o);
        if (lane >= o) v += n;
    }
    if (lane == 31) warp_sums[wid] = v;
    __syncthreads();
    if (wid == 0) {
        int w = (lane < 8) ? warp_sums[lane] : 0;
#pragma unroll
        for (int o = 1; o < 8; o <<= 1) {
            int n = __shfl_up_sync(0xffffffffu, w, o);
            if (lane >= o) w += n;
        }
        if (lane < 8) warp_sums[lane] = w;
    }
    __syncthreads();
    return v + (wid > 0 ? warp_sums[wid - 1] : 0);
}

__global__ void k_scan1() {
    __shared__ int ws[8];
    int i = blockIdx.x * 256 + threadIdx.x;
    if (i < NN) {                           // fused dinv
        float d = g_deg[i];
        g_dinv[i] = d > 0.f ? rsqrtf(fmaxf(d, 1e-12f)) : 0.f;
    }
    int val = (i < NN) ? g_cnt[i] : 0;
    int incl = block_incl_scan(val, ws);
    if (threadIdx.x == 255) g_part[blockIdx.x] = incl;
}

__global__ void k_scan2() {
    __shared__ int ws[8];
    int t = threadIdx.x;
    int val = (t < NP) ? g_part[t] : 0;
    int incl = block_incl_scan(val, ws);
    if (t < NP) g_partscan[t] = incl - val;   // exclusive
}

__global__ void k_scan3() {
    __shared__ int ws[8];
    int i = blockIdx.x * 256 + threadIdx.x;
    int val = (i < NN) ? g_cnt[i] : 0;
    int incl = block_incl_scan(val, ws);
    int excl = incl - val + g_partscan[blockIdx.x];
    if (i < NN) { g_rowstart[i] = excl; g_cursor[i] = excl; }
    if (i == 0) g_rowstart[NN] = EE;
}

__global__ void k_scatter(const int* __restrict__ row, const int* __restrict__ col,
                          const float* __restrict__ w) {
    int e = blockIdx.x * blockDim.x + threadIdx.x;
    if (e < EE) {
        int r = row[e];
        int c = col[e];
        int pos = atomicAdd(&g_cursor[r], 1);
        g_ecol[pos] = c;
        g_ew2[pos] = w[e] * g_dinv[c];
    }
}

// ---------------- propagate bodies ----------------
__device__ void prop256_body(int i, const float* __restrict__ h,
                             float* __restrict__ out, const float* __restrict__ bias) {
    int c = threadIdx.x;
    __shared__ int scol[256];
    __shared__ float sw[256];

    int s = g_rowstart[i], e = g_rowstart[i + 1];
    float hc = h[((size_t)i << 8) + c];
    float acc0 = 0.f, acc1 = 0.f, acc2 = 0.f, acc3 = 0.f;

    for (int base = s; base < e; base += 256) {
        int n = e - base; if (n > 256) n = 256;
        if (c < n) { scol[c] = g_ecol[base + c]; sw[c] = g_ew2[base + c]; }
        __syncthreads();
        int j = 0;
        for (; j + 3 < n; j += 4) {
            acc0 += sw[j + 0] * h[((size_t)scol[j + 0] << 8) + c];
            acc1 += sw[j + 1] * h[((size_t)scol[j + 1] << 8) + c];
            acc2 += sw[j + 2] * h[((size_t)scol[j + 2] << 8) + c];
            acc3 += sw[j + 3] * h[((size_t)scol[j + 3] << 8) + c];
        }
        for (; j < n; j++)
            acc0 += sw[j] * h[((size_t)scol[j] << 8) + c];
        __syncthreads();
    }
    float di = g_dinv[i];
    float acc = (acc0 + acc1) + (acc2 + acc3);
    float b = bias ? bias[c] : 0.f;
    out[((size_t)i << 8) + c] = di * di * hc + di * acc + b;
}

template <bool DUAL>
__device__ void prop40_body(int i,
                            const float* __restrict__ ha, const float* __restrict__ hb,
                            float* __restrict__ oa, float* __restrict__ ob,
                            const float* __restrict__ bias) {
    int lane = threadIdx.x & 31;
    int s = g_rowstart[i], e = g_rowstart[i + 1];
    float a0 = 0.f, a1 = 0.f, b0 = 0.f, b1 = 0.f;

    for (int p = s; p < e; p++) {
        int c = g_ecol[p];
        float w = g_ew2[p];
        const float* ra = ha + (size_t)c * OUTC;
        a0 += w * ra[lane];
        if (lane < 8) a1 += w * ra[lane + 32];
        if (DUAL) {
            const float* rb = hb + (size_t)c * OUTC;
            b0 += w * rb[lane];
            if (lane < 8) b1 += w * rb[lane + 32];
        }
    }
    float di = g_dinv[i];
    size_t off = (size_t)i * OUTC;
    float bs0 = bias ? bias[lane] : 0.f;
    float bs1 = (bias && lane < 8) ? bias[lane + 32] : 0.f;

    oa[off + lane] = di * di * ha[off + lane] + di * a0 + bs0;
    if (lane < 8)
        oa[off + lane + 32] = di * di * ha[off + lane + 32] + di * a1 + bs1;
    if (DUAL) {
        ob[off + lane] = di * di * hb[off + lane] + di * b0;
        if (lane < 8)
            ob[off + lane + 32] = di * di * hb[off + lane + 32] + di * b1;
    }
}

// ---------------- batchnorm ----------------
__global__ void k_bn_reduce(const float* __restrict__ h) {
    int c = threadIdx.x;
    float s = 0.f, sq = 0.f;
    for (int i = blockIdx.x; i < NN; i += gridDim.x) {
        float v = h[((size_t)i << 8) + c];
        s += v;
        sq += v * v;
    }
    atomicAdd(&g_sum[c], s);
    atomicAdd(&g_sumsq[c], sq);
}

__global__ void k_bn_finalize(const float* __restrict__ gamma, const float* __restrict__ beta) {
    int c = threadIdx.x;
    float mean = g_sum[c] * (1.0f / NN);
    float var = g_sumsq[c] * (1.0f / NN) - mean * mean;
    var = fmaxf(var, 0.f);
    float inv = rsqrtf(var + BN_EPS);
    float sc = gamma[c] * inv;
    g_scale[c] = sc;
    g_shift[c] = beta[c] - mean * sc;
}

// ---------------- bf16x3 split tensor-core GEMM body ----------------
#define AS_ST 24    // bf16 units per A row (16 data + 8 pad)
#define BS_ST 136   // bf16 units per B k-row (128 data + 8 pad)

__device__ __forceinline__ void ldsm_x4(uint32_t* r, uint32_t addr) {
    asm volatile("ldmatrix.sync.aligned.m8n8.x4.shared.b16 {%0,%1,%2,%3}, [%4];"
                 : "=r"(r[0]), "=r"(r[1]), "=r"(r[2]), "=r"(r[3]) : "r"(addr));
}
__device__ __forceinline__ void ldsm_x2_t(uint32_t* r, uint32_t addr) {
    asm volatile("ldmatrix.sync.aligned.m8n8.x2.trans.shared.b16 {%0,%1}, [%2];"
                 : "=r"(r[0]), "=r"(r[1]) : "r"(addr));
}
__device__ __forceinline__ void mma_bf16(float* c, const uint32_t* a, const uint32_t* b) {
    asm volatile(
        "mma.sync.aligned.m16n8k16.row.col.f32.bf16.bf16.f32 "
        "{%0,%1,%2,%3}, {%4,%5,%6,%7}, {%8,%9}, {%0,%1,%2,%3};"
        : "+f"(c[0]), "+f"(c[1]), "+f"(c[2]), "+f"(c[3])
        : "r"(a[0]), "r"(a[1]), "r"(a[2]), "r"(a[3]), "r"(b[0]), "r"(b[1]));
}

__device__ __forceinline__ void split_bf16(float x, __nv_bfloat16& h, __nv_bfloat16& l) {
    h = __float2bfloat16_rn(x);
    l = __float2bfloat16_rn(x - __bfloat162float(h));
}

template <bool FUSE_BN>
__device__ void gemm_body(int bm, int bn, int M, int N, int K,
                          const float* __restrict__ A, const float* __restrict__ B,
                          float* __restrict__ C) {
    __shared__ __nv_bfloat16 Ah[128 * AS_ST];
    __shared__ __nv_bfloat16 Al[128 * AS_ST];
    __shared__ __nv_bfloat16 Bh[16 * BS_ST];
    __shared__ __nv_bfloat16 Bl[16 * BS_ST];

    int tid = threadIdx.x;
    int aRow = tid >> 1;
    int aK   = (tid & 1) * 8;
    int bK   = tid >> 4;
    int bN   = (tid & 15) * 8;

    int warp = tid >> 5, lane = tid & 31;
    int wm = (warp >> 1) * 32;
    int wn = (warp & 1) * 64;
    int groupID = lane >> 2, tig = lane & 3;

    uint32_t sAh = (uint32_t)__cvta_generic_to_shared(Ah);
    uint32_t sAl = (uint32_t)__cvta_generic_to_shared(Al);
    uint32_t sBh = (uint32_t)__cvta_generic_to_shared(Bh);
    uint32_t sBl = (uint32_t)__cvta_generic_to_shared(Bl);

    uint32_t aAddrH[2], aAddrL[2];
#pragma unroll
    for (int mi = 0; mi < 2; mi++) {
        int ar = wm + mi * 16 + (lane & 7) + ((lane >> 3) & 1) * 8;
        int ako = (lane & 16) ? 8 : 0;
        uint32_t off = (uint32_t)(ar * AS_ST + ako) * 2;
        aAddrH[mi] = sAh + off;
        aAddrL[mi] = sAl + off;
    }
    int bk = ((lane & 15) >> 3) * 8 + (lane & 7);
    uint32_t bRowOffH = sBh + (uint32_t)(bk * BS_ST) * 2;
    uint32_t bRowOffL = sBl + (uint32_t)(bk * BS_ST) * 2;

    float acc[2][8][4];
#pragma unroll
    for (int mi = 0; mi < 2; mi++)
#pragma unroll
        for (int ni = 0; ni < 8; ni++)
#pragma unroll
            for (int q = 0; q < 4; q++) acc[mi][ni][q] = 0.f;

    float4 aPf[2], bPf[2];

    {
        int grow = bm + aRow;
#pragma unroll
        for (int q = 0; q < 2; q++) {
            aPf[q] = make_float4(0.f, 0.f, 0.f, 0.f);
            if (grow < M) aPf[q] = *(const float4*)(A + (size_t)grow * K + aK + q * 4);
        }
#pragma unroll
        for (int q = 0; q < 2; q++) {
            int gn = bn + bN + q * 4;
            float4 v = make_float4(0.f, 0.f, 0.f, 0.f);
            if (gn + 3 < N) v = *(const float4*)(B + (size_t)bK * N + gn);
            else {
                const float* Bp = B + (size_t)bK * N + gn;
                if (gn + 0 < N) v.x = Bp[0];
                if (gn + 1 < N) v.y = Bp[1];
                if (gn + 2 < N) v.z = Bp[2];
            }
            bPf[q] = v;
        }
    }

    for (int k0 = 0; k0 < K; k0 += 16) {
#pragma unroll
        for (int q = 0; q < 2; q++) {
            float4 v = aPf[q];
            if (FUSE_BN) {
                int k = k0 + aK + q * 4;
                v.x = fmaxf(v.x * g_scale[k + 0] + g_shift[k + 0], 0.f);
                v.y = fmaxf(v.y * g_scale[k + 1] + g_shift[k + 1], 0.f);
                v.z = fmaxf(v.z * g_scale[k + 2] + g_shift[k + 2], 0.f);
                v.w = fmaxf(v.w * g_scale[k + 3] + g_shift[k + 3], 0.f);
            }
            __nv_bfloat16 h0, l0, h1, l1, h2, l2, h3, l3;
            split_bf16(v.x, h0, l0); split_bf16(v.y, h1, l1);
            split_bf16(v.z, h2, l2); split_bf16(v.w, h3, l3);
            int off = aRow * AS_ST + aK + q * 4;
            *(__nv_bfloat162*)(Ah + off)     = __nv_bfloat162(h0, h1);
            *(__nv_bfloat162*)(Ah + off + 2) = __nv_bfloat162(h2, h3);
            *(__nv_bfloat162*)(Al + off)     = __nv_bfloat162(l0, l1);
            *(__nv_bfloat162*)(Al + off + 2) = __nv_bfloat162(l2, l3);
        }
#pragma unroll
        for (int q = 0; q < 2; q++) {
            float4 v = bPf[q];
            __nv_bfloat16 h0, l0, h1, l1, h2, l2, h3, l3;
            split_bf16(v.x, h0, l0); split_bf16(v.y, h1, l1);
            split_bf16(v.z, h2, l2); split_bf16(v.w, h3, l3);
            int off = bK * BS_ST + bN + q * 4;
            *(__nv_bfloat162*)(Bh + off)     = __nv_bfloat162(h0, h1);
            *(__nv_bfloat162*)(Bh + off + 2) = __nv_bfloat162(h2, h3);
            *(__nv_bfloat162*)(Bl + off)     = __nv_bfloat162(l0, l1);
            *(__nv_bfloat162*)(Bl + off + 2) = __nv_bfloat162(l2, l3);
        }
        __syncthreads();

        if (k0 + 16 < K) {
            int grow = bm + aRow;
#pragma unroll
            for (int q = 0; q < 2; q++) {
                aPf[q] = make_float4(0.f, 0.f, 0.f, 0.f);
                if (grow < M) aPf[q] = *(const float4*)(A + (size_t)grow * K + k0 + 16 + aK + q * 4);
            }
#pragma unroll
            for (int q = 0; q < 2; q++) {
                int gn = bn + bN + q * 4;
                float4 v = make_float4(0.f, 0.f, 0.f, 0.f);
                if (gn + 3 < N) v = *(const float4*)(B + (size_t)(k0 + 16 + bK) * N + gn);
                else {
                    const float* Bp = B + (size_t)(k0 + 16 + bK) * N + gn;
                    if (gn + 0 < N) v.x = Bp[0];
                    if (gn + 1 < N) v.y = Bp[1];
                    if (gn + 2 < N) v.z = Bp[2];
                }
                bPf[q] = v;
            }
        }

        uint32_t ah[2][4], al[2][4];
#pragma unroll
        for (int mi = 0; mi < 2; mi++) {
            ldsm_x4(ah[mi], aAddrH[mi]);
            ldsm_x4(al[mi], aAddrL[mi]);
        }
#pragma unroll
        for (int ni = 0; ni < 8; ni++) {
            uint32_t coff = (uint32_t)(wn + ni * 8) * 2;
            uint32_t bh[2], bl[2];
            ldsm_x2_t(bh, bRowOffH + coff);
            ldsm_x2_t(bl, bRowOffL + coff);
#pragma unroll
            for (int mi = 0; mi < 2; mi++) {
                mma_bf16(acc[mi][ni], ah[mi], bh);
                mma_bf16(acc[mi][ni], al[mi], bh);
                mma_bf16(acc[mi][ni], ah[mi], bl);
            }
        }
        __syncthreads();
    }

#pragma unroll
    for (int mi = 0; mi < 2; mi++) {
        int r0 = bm + wm + mi * 16 + groupID;
        int r1 = r0 + 8;
#pragma unroll
        for (int ni = 0; ni < 8; ni++) {
            int c0 = bn + wn + ni * 8 + 2 * tig;
            if (r0 < M) {
                if (c0 < N)     C[(size_t)r0 * N + c0]     = acc[mi][ni][0];
                if (c0 + 1 < N) C[(size_t)r0 * N + c0 + 1] = acc[mi][ni][1];
            }
            if (r1 < M) {
                if (c0 < N)     C[(size_t)r1 * N + c0]     = acc[mi][ni][2];
                if (c0 + 1 < N) C[(size_t)r1 * N + c0 + 1] = acc[mi][ni][3];
            }
        }
    }
}

// ---------------- standalone kernels ----------------
template <bool FUSE_BN>
__global__ void __launch_bounds__(256) k_gemm(int M, int N, int K,
                                              const float* __restrict__ A,
                                              const float* __restrict__ B,
                                              float* __restrict__ C) {
    gemm_body<FUSE_BN>(blockIdx.y * 128, blockIdx.x * 128, M, N, K, A, B, C);
}

__global__ void __launch_bounds__(256) k_prop40_single(const float* __restrict__ ha,
                                                       float* __restrict__ oa,
                                                       const float* __restrict__ bias) {
    int i = blockIdx.x * 8 + (threadIdx.x >> 5);
    if (i < NN) prop40_body<false>(i, ha, nullptr, oa, nullptr, bias);
}

// ---------------- fused kernels ----------------
// A: GEMM0 (no BN) || LPA iter 1
__global__ void __launch_bounds__(256) k_fusedA(const float* __restrict__ A,
                                                const float* __restrict__ B,
                                                float* __restrict__ C,
                                                const float* __restrict__ pa,
                                                const float* __restrict__ pb,
                                                float* __restrict__ oa,
                                                float* __restrict__ ob) {
    if (blockIdx.x < G0B) {
        gemm_body<false>((blockIdx.x >> 1) * 128, (blockIdx.x & 1) * 128,
                         NN, HIDC, INC, A, B, C);
    } else {
        int i = (blockIdx.x - G0B) * 8 + (threadIdx.x >> 5);
        if (i < NN) prop40_body<true>(i, pa, pb, oa, ob, nullptr);
    }
}

// B/C: prop256 || LPA iter || BN-zero
__global__ void __launch_bounds__(256) k_fusedP(const float* __restrict__ h,
                                                float* __restrict__ out,
                                                const float* __restrict__ bias,
                                                const float* __restrict__ pa,
                                                const float* __restrict__ pb,
                                                float* __restrict__ oa,
                                                float* __restrict__ ob) {
    if (blockIdx.x < NN) {
        prop256_body(blockIdx.x, h, out, bias);
    } else if (blockIdx.x < NN + L40B) {
        int i = (blockIdx.x - NN) * 8 + (threadIdx.x >> 5);
        if (i < NN) prop40_body<true>(i, pa, pb, oa, ob, nullptr);
    } else {
        g_sum[threadIdx.x] = 0.f;
        g_sumsq[threadIdx.x] = 0.f;
    }
}

// ---------------- host orchestration ----------------
static inline int cdiv(int a, int b) { return (a + b - 1) / b; }

extern "C" void kernel_launch(void* const* d_in, const int* in_sizes, int n_in,
                              void* d_out, int out_size) {
    const float* x    = (const float*)d_in[0];
    const int*   ei   = (const int*)  d_in[1];
    const float* lab  = (const float*)d_in[2];
    const float* lab2 = (const float*)d_in[3];
    const float* ew   = (const float*)d_in[4];
    const float* W0   = (const float*)d_in[5];
    const float* b0   = (const float*)d_in[6];
    const float* W1   = (const float*)d_in[7];
    const float* b1   = (const float*)d_in[8];
    const float* W2   = (const float*)d_in[9];
    const float* b2   = (const float*)d_in[10];
    const float* g0   = (const float*)d_in[11];
    const float* be0  = (const float*)d_in[12];
    const float* g1   = (const float*)d_in[13];
    const float* be1  = (const float*)d_in[14];
    float* out = (float*)d_out;

    const int* row = ei;
    const int* col = ei + EE;

    float *t1, *t2, *t3, *la, *lb, *lc, *ld;
    cudaGetSymbolAddress((void**)&t1, g_t1);
    cudaGetSymbolAddress((void**)&t2, g_t2);
    cudaGetSymbolAddress((void**)&t3, g_t3);
    cudaGetSymbolAddress((void**)&la, g_la);
    cudaGetSymbolAddress((void**)&lb, g_lb);
    cudaGetSymbolAddress((void**)&lc, g_lc);
    cudaGetSymbolAddress((void**)&ld, g_ld);

    const int T = 256;
    float* yh1 = out + (size_t)NN * OUTC;
    float* yh2 = out + (size_t)2 * NN * OUTC;

    // ---- CSR + normalization ----
    k_init_node<<<cdiv(NN, T), T>>>();
    k_deg_cnt<<<cdiv(EE, T), T>>>(row, ew);
    k_scan1<<<NP, 256>>>();                  // also computes dinv
    k_scan2<<<1, 256>>>();
    k_scan3<<<NP, 256>>>();
    k_scatter<<<cdiv(EE, T), T>>>(row, col, ew);

    // ---- A: GEMM0 (x@W0 -> t1) || LPA iter1 (lab,lab2 -> la,lb) ----
    k_fusedA<<<G0B + L40B, T>>>(x, W0, t1, lab, lab2, la, lb);

    // ---- B: prop256 (t1 -> t2, +b0) || LPA iter2 (la,lb -> lc,ld) || BN zero ----
    k_fusedP<<<NN + L40B + 1, T>>>(t1, t2, b0, la, lb, lc, ld);
    k_bn_reduce<<<256, HIDC>>>(t2);
    k_bn_finalize<<<1, HIDC>>>(g0, be0);

    // ---- GEMM1: relu(bn(t2))@W1 -> t1 ----
    k_gemm<true><<<dim3(2, cdiv(NN, 128)), T>>>(NN, HIDC, HIDC, t2, W1, t1);

    // ---- C: prop256 (t1 -> t2, +b1) || LPA iter3 (lc,ld -> yh1,yh2) || BN zero ----
    k_fusedP<<<NN + L40B + 1, T>>>(t1, t2, b1, lc, ld, yh1, yh2);
    k_bn_reduce<<<256, HIDC>>>(t2);
    k_bn_finalize<<<1, HIDC>>>(g1, be1);

    // ---- GEMM2: relu(bn(t2))@W2 -> t3 ; final prop40 -> d_out ----
    k_gemm<true><<<dim3(1, cdiv(NN, 128)), T>>>(NN, OUTC, HIDC, t2, W2, t3);
    k_prop40_single<<<L40B, T>>>(t3, out, b2);
}